// round 11
// baseline (speedup 1.0000x reference)
#include <cuda_runtime.h>
#include <cuda_fp16.h>
#include <cstdint>

#define NMAX 100000
#define EMAX 3200000
#define CAP 128                       // padded row capacity (deg ~ Poisson(32))
#define PB_BLOCKS 1184
#define FULLMASK 0xFFFFFFFFu

// ---------------- device scratch (no allocations allowed) ----------------
static __device__ int      g_deg[NMAX];          // in-edge count (excl. self)
static __device__ unsigned g_qh[NMAX];           // half2(q.x, q.y), q = dis*x
static __device__ float    g_dis[NMAX];          // (deg+1)^-1/2
static __device__ int      g_cols[(size_t)NMAX * CAP]; // padded adjacency
static __device__ uint4    g_rh[NMAX];           // {h2(rx,rx), h2(ry,ry), h2(rz,rz), f32 rz}
static __device__ double   g_part[PB_BLOCKS];    // per-block head partials
static __device__ int      g_is64;               // 1 if edge_index is int64

__device__ __forceinline__ int clampi(int v, int n) {
    return v < 0 ? 0 : (v >= n ? n - 1 : v);
}
__device__ __forceinline__ unsigned h2_to_u(half2 h) {
    return *reinterpret_cast<unsigned*>(&h);
}
__device__ __forceinline__ half2 u_to_h2(unsigned u) {
    return *reinterpret_cast<half2*>(&u);
}

// ---------------- kernels ----------------

// zero deg + parallel dtype probe (block 0)
__global__ void k_init(const void* ei, int E, long long N64, int N) {
    int i = blockIdx.x * blockDim.x + threadIdx.x;
    if (i < N) g_deg[i] = 0;
    if (blockIdx.x == 0) {
        __shared__ int bad;
        if (threadIdx.x == 0) bad = 0;
        __syncthreads();
        int cnt = E > 256 ? 256 : E;
        if (threadIdx.x < cnt) {
            unsigned long long w = ((const unsigned long long*)ei)[threadIdx.x];
            if (w >= (unsigned long long)N64) bad = 1;
        }
        __syncthreads();
        if (threadIdx.x == 0) g_is64 = bad ? 0 : 1;
    }
}

// Single edge pass: histogram AND adjacency build. 2 edges per thread.
__global__ void k_build(const void* __restrict__ ei, int E, int N) {
    int t = blockIdx.x * blockDim.x + threadIdx.x;
    int e0 = t * 2;
    if (e0 >= E) return;
    int is64 = g_is64;
    bool two = (e0 + 1 < E);
    bool vec = two && ((E & 1) == 0);
    int s0, s1 = 0, d0, d1 = 0;
    if (is64) {
        const long long* p = (const long long*)ei;
        if (vec) {
            longlong2 ss = *(const longlong2*)&p[e0];
            longlong2 dd = *(const longlong2*)&p[(size_t)E + e0];
            s0 = (int)ss.x; s1 = (int)ss.y; d0 = (int)dd.x; d1 = (int)dd.y;
        } else {
            s0 = (int)p[e0]; d0 = (int)p[(size_t)E + e0];
            if (two) { s1 = (int)p[e0 + 1]; d1 = (int)p[(size_t)E + e0 + 1]; }
        }
    } else {
        const int* p = (const int*)ei;
        if (vec) {
            int2 ss = *(const int2*)&p[e0];
            int2 dd = *(const int2*)&p[(size_t)E + e0];
            s0 = ss.x; s1 = ss.y; d0 = dd.x; d1 = dd.y;
        } else {
            s0 = p[e0]; d0 = p[(size_t)E + e0];
            if (two) { s1 = p[e0 + 1]; d1 = p[(size_t)E + e0 + 1]; }
        }
    }
    s0 = clampi(s0, N); d0 = clampi(d0, N);
    int p0 = atomicAdd(&g_deg[d0], 1);
    if (p0 < CAP) g_cols[(size_t)d0 * CAP + p0] = s0;
    if (two) {
        s1 = clampi(s1, N); d1 = clampi(d1, N);
        int p1 = atomicAdd(&g_deg[d1], 1);
        if (p1 < CAP) g_cols[(size_t)d1 * CAP + p1] = s1;
    }
}

// dis = rsqrt(deg+1);  qh = half2(dis*x)
__global__ void k_dis(const float* __restrict__ x, int N) {
    int i = blockIdx.x * blockDim.x + threadIdx.x;
    if (i < N) {
        float dis = rsqrtf((float)(g_deg[i] + 1));
        g_dis[i] = dis;
        float2 xv = ((const float2*)x)[i];
        g_qh[i] = h2_to_u(__floats2half2_rn(dis * xv.x, dis * xv.y));
    }
}

// Pass A: 8 lanes per node (4 nodes per warp); 4 independent gathers in
// flight per lane (MLP~4). rh[i] = {h2(rx), h2(ry), h2(dis), f32 dis}
__global__ void k_passA(int N) {
    int warp = (blockIdx.x * blockDim.x + threadIdx.x) >> 5;
    int lane = threadIdx.x & 31;
    int sub  = lane >> 3;            // node slot within warp (0..3)
    int sl   = lane & 7;             // lane within 8-lane group
    unsigned gmask = 0xFFu << (sub * 8);
    int w = warp * 4 + sub;
    if (w >= N) return;              // group-uniform exit

    int cnt = g_deg[w]; if (cnt > CAP) cnt = CAP;
    const int* row = &g_cols[(size_t)w * CAP];

    float sx0 = 0.f, sy0 = 0.f, sx1 = 0.f, sy1 = 0.f;
    float sx2 = 0.f, sy2 = 0.f, sx3 = 0.f, sy3 = 0.f;
    int j = sl;
    for (; j + 24 < cnt; j += 32) {          // 4 gathers in flight
        float2 a = __half22float2(u_to_h2(g_qh[row[j]]));
        float2 b = __half22float2(u_to_h2(g_qh[row[j + 8]]));
        float2 c = __half22float2(u_to_h2(g_qh[row[j + 16]]));
        float2 d = __half22float2(u_to_h2(g_qh[row[j + 24]]));
        sx0 += a.x; sy0 += a.y;
        sx1 += b.x; sy1 += b.y;
        sx2 += c.x; sy2 += c.y;
        sx3 += d.x; sy3 += d.y;
    }
    for (; j < cnt; j += 8) {
        float2 a = __half22float2(u_to_h2(g_qh[row[j]]));
        sx0 += a.x; sy0 += a.y;
    }
    float sx = (sx0 + sx1) + (sx2 + sx3);
    float sy = (sy0 + sy1) + (sy2 + sy3);
    #pragma unroll
    for (int o = 4; o > 0; o >>= 1) {        // 3-level reduce within group
        sx += __shfl_xor_sync(gmask, sx, o);
        sy += __shfl_xor_sync(gmask, sy, o);
    }
    if (sl == 0) {
        float dd = g_dis[w];
        float2 qi = __half22float2(u_to_h2(g_qh[w]));
        float ax = dd * (sx + qi.x);         // agg2.x
        float ay = dd * (sy + qi.y);         // agg2.y
        float rx = dd * ax, ry = dd * ay;
        g_rh[w] = make_uint4(h2_to_u(__float2half2_rn(rx)),
                             h2_to_u(__float2half2_rn(ry)),
                             h2_to_u(__float2half2_rn(dd)),
                             __float_as_uint(dd));
    }
}

// Fused pass B + W2 + head. Warp per dst; lane owns features 2l, 2l+1.
// Edge loop: fp16x2 (R8 structure). Head: fp16x2 packed W2 (per-lane-
// contiguous half2 layout, LDS.128 = 4 k's), two 32-k chains flushed to fp32.
__global__ void __launch_bounds__(256) k_passB(
        const float* __restrict__ W1, const float* __restrict__ b1,
        const float* __restrict__ W2, const float* __restrict__ b2,
        const float* __restrict__ Wl, int N) {
    __shared__ unsigned w2h[32 * 64];     // [lane][k] half2(W2[k][2l],W2[k][2l+1])
    __shared__ uint4    stage[8][32];
    __shared__ unsigned mh[8][64];        // 64 splatted half2 m-values per warp
    __shared__ double   wsum[8];

    for (int idx = threadIdx.x; idx < 32 * 64; idx += blockDim.x) {
        int l = idx >> 6, k = idx & 63;
        w2h[idx] = h2_to_u(__floats2half2_rn(W2[k * 64 + 2 * l],
                                             W2[k * 64 + 2 * l + 1]));
    }
    __syncthreads();

    int lane = threadIdx.x & 31;
    int wib  = threadIdx.x >> 5;
    int gw   = blockIdx.x * 8 + wib;
    int nw   = gridDim.x * 8;

    half2 W1A2 = __floats2half2_rn(W1[2 * lane],      W1[2 * lane + 1]);
    half2 W1B2 = __floats2half2_rn(W1[64 + 2 * lane], W1[64 + 2 * lane + 1]);
    half2 B12  = __floats2half2_rn(b1[2 * lane],      b1[2 * lane + 1]);
    half2 zero2 = __floats2half2_rn(0.f, 0.f);

    float bb20 = b2[2 * lane], bb21 = b2[2 * lane + 1];
    float wl0  = Wl[2 * lane], wl1  = Wl[2 * lane + 1];

    const uint4* wq = (const uint4*)&w2h[lane * 64];   // 4 half2 per load
    float headacc = 0.f;

    for (int w = gw; w < N; w += nw) {
        int cnt = g_deg[w]; if (cnt > CAP) cnt = CAP;
        const int* row = &g_cols[(size_t)w * CAP];
        uint4 self = g_rh[w];
        float rz = __uint_as_float(self.w);

        float a0 = 0.f, a1 = 0.f;
        half2 acc2;
        {
            half2 t = __hfma2(u_to_h2(self.x), W1A2,
                      __hfma2(u_to_h2(self.y), W1B2,
                      __hmul2(u_to_h2(self.z), B12)));
            acc2 = __hmax2(t, zero2);
        }

        int base = 0;
        for (; base + 32 <= cnt; base += 32) {
            stage[wib][lane] = g_rh[row[base + lane]];
            __syncwarp();
            #pragma unroll
            for (int k = 0; k < 32; k++) {
                uint4 v = stage[wib][k];
                half2 t = __hfma2(u_to_h2(v.x), W1A2,
                          __hfma2(u_to_h2(v.y), W1B2,
                          __hmul2(u_to_h2(v.z), B12)));
                acc2 = __hadd2(acc2, __hmax2(t, zero2));
            }
            __syncwarp();
            float2 f = __half22float2(acc2);   // flush block to fp32
            a0 += f.x; a1 += f.y;
            acc2 = zero2;
        }
        {
            int rem = cnt - base;
            if (lane < rem) stage[wib][lane] = g_rh[row[base + lane]];
            __syncwarp();
            for (int k = 0; k < rem; k++) {
                uint4 v = stage[wib][k];
                half2 t = __hfma2(u_to_h2(v.x), W1A2,
                          __hfma2(u_to_h2(v.y), W1B2,
                          __hmul2(u_to_h2(v.z), B12)));
                acc2 = __hadd2(acc2, __hmax2(t, zero2));
            }
            __syncwarp();
            float2 f = __half22float2(acc2);
            a0 += f.x; a1 += f.y;
        }

        float m0 = rz * a0;
        float m1 = rz * a1;

        // stage m as splatted half2 (lane l -> slots 2l, 2l+1)
        ((uint2*)mh[wib])[lane] =
            make_uint2(h2_to_u(__float2half2_rn(m0)),
                       h2_to_u(__float2half2_rn(m1)));
        __syncwarp();

        // head: v = m @ W2 + b2 in fp16x2, two 32-k chains flushed to fp32
        float s0 = bb20, s1 = bb21;
        const uint4* mq = (const uint4*)mh[wib];       // 4 half2 per load
        #pragma unroll
        for (int hf = 0; hf < 2; hf++) {
            half2 hv0 = zero2, hv1 = zero2;
            #pragma unroll
            for (int g = hf * 8; g < hf * 8 + 8; g++) {
                uint4 mm = mq[g];
                uint4 ww = wq[g];
                hv0 = __hfma2(u_to_h2(mm.x), u_to_h2(ww.x), hv0);
                hv0 = __hfma2(u_to_h2(mm.y), u_to_h2(ww.y), hv0);
                hv1 = __hfma2(u_to_h2(mm.z), u_to_h2(ww.z), hv1);
                hv1 = __hfma2(u_to_h2(mm.w), u_to_h2(ww.w), hv1);
            }
            float2 f0 = __half22float2(hv0);
            float2 f1 = __half22float2(hv1);
            s0 += f0.x + f1.x;
            s1 += f0.y + f1.y;
        }
        __syncwarp();
        headacc += fmaxf(s0, 0.f) * wl0 + fmaxf(s1, 0.f) * wl1;
    }

    #pragma unroll
    for (int o = 16; o > 0; o >>= 1)
        headacc += __shfl_xor_sync(FULLMASK, headacc, o);
    if (lane == 0) wsum[wib] = (double)headacc;
    __syncthreads();
    if (threadIdx.x == 0) {
        double s = 0.0;
        #pragma unroll
        for (int t = 0; t < 8; t++) s += wsum[t];
        g_part[blockIdx.x] = s;
    }
}

// final reduce over block partials
__global__ void k_final(const float* __restrict__ bl, float* __restrict__ out, int N) {
    __shared__ double sh[256];
    double s = 0.0;
    for (int i = threadIdx.x; i < PB_BLOCKS; i += 256) s += g_part[i];
    sh[threadIdx.x] = s;
    __syncthreads();
    for (int off = 128; off > 0; off >>= 1) {
        if (threadIdx.x < off) sh[threadIdx.x] += sh[threadIdx.x + off];
        __syncthreads();
    }
    if (threadIdx.x == 0) out[0] = (float)(sh[0] / (double)N) + bl[0];
}

// ---------------- launcher ----------------
// inputs: 0:x[N,2] f32  1:edge_index[2,E] int32/int64  2:W1[2,64]  3:b1[64]
//         4:W2[64,64]   5:b2[64]   6:Wl[64,1]  7:bl[1]
extern "C" void kernel_launch(void* const* d_in, const int* in_sizes, int n_in,
                              void* d_out, int out_size) {
    const float* x  = (const float*)d_in[0];
    const void*  ei = d_in[1];
    const float* W1 = (const float*)d_in[2];
    const float* b1 = (const float*)d_in[3];
    const float* W2 = (const float*)d_in[4];
    const float* b2 = (const float*)d_in[5];
    const float* Wl = (const float*)d_in[6];
    const float* bl = (const float*)d_in[7];
    float* out = (float*)d_out;

    int N = in_sizes[0] / 2;
    if (N > NMAX) N = NMAX;
    int E = in_sizes[1] / 2;
    if (E > EMAX) E = EMAX;
    int Ehalf = (E + 1) / 2;
    int nodes_per_blk = 32;   // 8 warps * 4 nodes

    k_init <<<(N + 255) / 256, 256>>>(ei, E, (long long)N, N);
    k_build<<<(Ehalf + 255) / 256, 256>>>(ei, E, N);
    k_dis  <<<(N + 255) / 256, 256>>>(x, N);
    k_passA<<<(N + nodes_per_blk - 1) / nodes_per_blk, 256>>>(N);
    k_passB<<<PB_BLOCKS, 256>>>(W1, b1, W2, b2, Wl, N);
    k_final<<<1, 256>>>(bl, out, N);
}

// round 12
// speedup vs baseline: 1.9104x; 1.9104x over previous
#include <cuda_runtime.h>
#include <cuda_fp16.h>
#include <cstdint>

#define NMAX 100000
#define EMAX 3200000
#define CAP 128                       // padded row capacity (deg ~ Poisson(32))
#define PB_BLOCKS 1184
#define FULLMASK 0xFFFFFFFFu

// ---------------- device scratch (no allocations allowed) ----------------
static __device__ int      g_deg[NMAX];          // in-edge count (excl. self)
static __device__ unsigned g_qh[NMAX];           // half2(q.x, q.y), q = dis*x
static __device__ float    g_dis[NMAX];          // (deg+1)^-1/2
static __device__ int      g_cols[(size_t)NMAX * CAP]; // padded adjacency
static __device__ uint4    g_rh[NMAX];           // {h2(rx,rx), h2(ry,ry), h2(rz,rz), f32 rz}
static __device__ double   g_part[PB_BLOCKS];    // per-block head partials
static __device__ int      g_is64;               // 1 if edge_index is int64

__device__ __forceinline__ int clampi(int v, int n) {
    return v < 0 ? 0 : (v >= n ? n - 1 : v);
}
__device__ __forceinline__ unsigned h2_to_u(half2 h) {
    return *reinterpret_cast<unsigned*>(&h);
}
__device__ __forceinline__ half2 u_to_h2(unsigned u) {
    return *reinterpret_cast<half2*>(&u);
}

// ---------------- kernels ----------------

// zero deg + parallel dtype probe (block 0)
__global__ void k_init(const void* ei, int E, long long N64, int N) {
    int i = blockIdx.x * blockDim.x + threadIdx.x;
    if (i < N) g_deg[i] = 0;
    if (blockIdx.x == 0) {
        __shared__ int bad;
        if (threadIdx.x == 0) bad = 0;
        __syncthreads();
        int cnt = E > 256 ? 256 : E;
        if (threadIdx.x < cnt) {
            unsigned long long w = ((const unsigned long long*)ei)[threadIdx.x];
            if (w >= (unsigned long long)N64) bad = 1;
        }
        __syncthreads();
        if (threadIdx.x == 0) g_is64 = bad ? 0 : 1;
    }
}

// Single edge pass: histogram AND adjacency build.
// 4 edges per thread with 4 independent vector loads up-front (MLP~4).
__global__ void k_build(const void* __restrict__ ei, int E, int N) {
    int t = blockIdx.x * blockDim.x + threadIdx.x;
    int e0 = t * 4;
    if (e0 >= E) return;
    int is64 = g_is64;
    int s[4], d[4];
    int cnt = E - e0; if (cnt > 4) cnt = 4;

    if (cnt == 4 && ((E & 1) == 0)) {
        if (is64) {
            const long long* p = (const long long*)ei;
            longlong2 sa = *(const longlong2*)&p[e0];
            longlong2 sb = *(const longlong2*)&p[e0 + 2];
            longlong2 da = *(const longlong2*)&p[(size_t)E + e0];
            longlong2 db = *(const longlong2*)&p[(size_t)E + e0 + 2];
            s[0] = (int)sa.x; s[1] = (int)sa.y; s[2] = (int)sb.x; s[3] = (int)sb.y;
            d[0] = (int)da.x; d[1] = (int)da.y; d[2] = (int)db.x; d[3] = (int)db.y;
        } else {
            const int* p = (const int*)ei;
            int2 sa = *(const int2*)&p[e0];
            int2 sb = *(const int2*)&p[e0 + 2];
            int2 da = *(const int2*)&p[(size_t)E + e0];
            int2 db = *(const int2*)&p[(size_t)E + e0 + 2];
            s[0] = sa.x; s[1] = sa.y; s[2] = sb.x; s[3] = sb.y;
            d[0] = da.x; d[1] = da.y; d[2] = db.x; d[3] = db.y;
        }
    } else {
        for (int k = 0; k < cnt; k++) {
            if (is64) {
                const long long* p = (const long long*)ei;
                s[k] = (int)p[e0 + k];
                d[k] = (int)p[(size_t)E + e0 + k];
            } else {
                const int* p = (const int*)ei;
                s[k] = p[e0 + k];
                d[k] = p[(size_t)E + e0 + k];
            }
        }
    }
    #pragma unroll
    for (int k = 0; k < 4; k++) {
        if (k < cnt) {
            int sv = clampi(s[k], N);
            int dv = clampi(d[k], N);
            int pos = atomicAdd(&g_deg[dv], 1);
            if (pos < CAP) g_cols[(size_t)dv * CAP + pos] = sv;
        }
    }
}

// dis = rsqrt(deg+1);  qh = half2(dis*x)
__global__ void k_dis(const float* __restrict__ x, int N) {
    int i = blockIdx.x * blockDim.x + threadIdx.x;
    if (i < N) {
        float dis = rsqrtf((float)(g_deg[i] + 1));
        g_dis[i] = dis;
        float2 xv = ((const float2*)x)[i];
        g_qh[i] = h2_to_u(__floats2half2_rn(dis * xv.x, dis * xv.y));
    }
}

// Pass A: 8 lanes per node (4 nodes per warp); dual gathers in flight.
// rh[i] = {h2(rx), h2(ry), h2(dis), f32 dis}
__global__ void k_passA(int N) {
    int warp = (blockIdx.x * blockDim.x + threadIdx.x) >> 5;
    int lane = threadIdx.x & 31;
    int sub  = lane >> 3;            // node slot within warp (0..3)
    int sl   = lane & 7;             // lane within 8-lane group
    unsigned gmask = 0xFFu << (sub * 8);
    int w = warp * 4 + sub;
    if (w >= N) return;              // group-uniform exit

    int cnt = g_deg[w]; if (cnt > CAP) cnt = CAP;
    const int* row = &g_cols[(size_t)w * CAP];

    float sx0 = 0.f, sy0 = 0.f, sx1 = 0.f, sy1 = 0.f;
    int j = sl;
    for (; j + 8 < cnt; j += 16) {           // dual-gather, MLP>=2
        float2 a = __half22float2(u_to_h2(g_qh[row[j]]));
        float2 b = __half22float2(u_to_h2(g_qh[row[j + 8]]));
        sx0 += a.x; sy0 += a.y;
        sx1 += b.x; sy1 += b.y;
    }
    if (j < cnt) {
        float2 a = __half22float2(u_to_h2(g_qh[row[j]]));
        sx0 += a.x; sy0 += a.y;
    }
    float sx = sx0 + sx1, sy = sy0 + sy1;
    #pragma unroll
    for (int o = 4; o > 0; o >>= 1) {        // 3-level reduce within group
        sx += __shfl_xor_sync(gmask, sx, o);
        sy += __shfl_xor_sync(gmask, sy, o);
    }
    if (sl == 0) {
        float dd = g_dis[w];
        float2 qi = __half22float2(u_to_h2(g_qh[w]));
        float ax = dd * (sx + qi.x);         // agg2.x
        float ay = dd * (sy + qi.y);         // agg2.y
        float rx = dd * ax, ry = dd * ay;
        g_rh[w] = make_uint4(h2_to_u(__float2half2_rn(rx)),
                             h2_to_u(__float2half2_rn(ry)),
                             h2_to_u(__float2half2_rn(dd)),
                             __float_as_uint(dd));
    }
}

// Fused pass B + W2 + head (exact R10 structure — the 163.9us winner).
// Warp per dst; lane owns features 2l, 2l+1. fp16x2 edge loop, fp32 head.
__global__ void __launch_bounds__(256) k_passB(
        const float* __restrict__ W1, const float* __restrict__ b1,
        const float* __restrict__ W2, const float* __restrict__ b2,
        const float* __restrict__ Wl, int N) {
    __shared__ float  W2s[64 * 64];
    __shared__ uint4  stage[8][32];
    __shared__ float  mbuf[8][64];
    __shared__ double wsum[8];

    for (int idx = threadIdx.x; idx < 64 * 64; idx += blockDim.x)
        W2s[idx] = W2[idx];
    __syncthreads();

    int lane = threadIdx.x & 31;
    int wib  = threadIdx.x >> 5;
    int gw   = blockIdx.x * 8 + wib;
    int nw   = gridDim.x * 8;

    half2 W1A2 = __floats2half2_rn(W1[2 * lane],      W1[2 * lane + 1]);
    half2 W1B2 = __floats2half2_rn(W1[64 + 2 * lane], W1[64 + 2 * lane + 1]);
    half2 B12  = __floats2half2_rn(b1[2 * lane],      b1[2 * lane + 1]);
    half2 zero2 = __floats2half2_rn(0.f, 0.f);

    float bb20 = b2[2 * lane], bb21 = b2[2 * lane + 1];
    float wl0  = Wl[2 * lane], wl1  = Wl[2 * lane + 1];

    const float2* W2v = (const float2*)W2s;
    float headacc = 0.f;

    for (int w = gw; w < N; w += nw) {
        int cnt = g_deg[w]; if (cnt > CAP) cnt = CAP;
        const int* row = &g_cols[(size_t)w * CAP];
        uint4 self = g_rh[w];
        float rz = __uint_as_float(self.w);

        float a0 = 0.f, a1 = 0.f;
        half2 acc2;
        {
            half2 t = __hfma2(u_to_h2(self.x), W1A2,
                      __hfma2(u_to_h2(self.y), W1B2,
                      __hmul2(u_to_h2(self.z), B12)));
            acc2 = __hmax2(t, zero2);
        }

        int base = 0;
        for (; base + 32 <= cnt; base += 32) {
            stage[wib][lane] = g_rh[row[base + lane]];
            __syncwarp();
            #pragma unroll
            for (int k = 0; k < 32; k++) {
                uint4 v = stage[wib][k];
                half2 t = __hfma2(u_to_h2(v.x), W1A2,
                          __hfma2(u_to_h2(v.y), W1B2,
                          __hmul2(u_to_h2(v.z), B12)));
                acc2 = __hadd2(acc2, __hmax2(t, zero2));
            }
            __syncwarp();
            float2 f = __half22float2(acc2);   // flush block to fp32
            a0 += f.x; a1 += f.y;
            acc2 = zero2;
        }
        {
            int rem = cnt - base;
            if (lane < rem) stage[wib][lane] = g_rh[row[base + lane]];
            __syncwarp();
            for (int k = 0; k < rem; k++) {
                uint4 v = stage[wib][k];
                half2 t = __hfma2(u_to_h2(v.x), W1A2,
                          __hfma2(u_to_h2(v.y), W1B2,
                          __hmul2(u_to_h2(v.z), B12)));
                acc2 = __hadd2(acc2, __hmax2(t, zero2));
            }
            __syncwarp();
            float2 f = __half22float2(acc2);
            a0 += f.x; a1 += f.y;
        }

        float m0 = rz * a0;
        float m1 = rz * a1;

        // head: v = m @ W2 + b2, via smem-staged m (4 values per LDS.128)
        ((float2*)mbuf[wib])[lane] = make_float2(m0, m1);
        __syncwarp();
        float v0 = bb20, v1 = bb21;
        const float4* mq = (const float4*)mbuf[wib];
        #pragma unroll
        for (int k = 0; k < 16; k++) {
            float4 mm = mq[k];
            float2 r0 = W2v[(size_t)(4 * k + 0) * 32 + lane];
            float2 r1 = W2v[(size_t)(4 * k + 1) * 32 + lane];
            float2 r2 = W2v[(size_t)(4 * k + 2) * 32 + lane];
            float2 r3 = W2v[(size_t)(4 * k + 3) * 32 + lane];
            v0 = fmaf(mm.x, r0.x, fmaf(mm.y, r1.x,
                 fmaf(mm.z, r2.x, fmaf(mm.w, r3.x, v0))));
            v1 = fmaf(mm.x, r0.y, fmaf(mm.y, r1.y,
                 fmaf(mm.z, r2.y, fmaf(mm.w, r3.y, v1))));
        }
        __syncwarp();
        headacc += fmaxf(v0, 0.f) * wl0 + fmaxf(v1, 0.f) * wl1;
    }

    #pragma unroll
    for (int o = 16; o > 0; o >>= 1)
        headacc += __shfl_xor_sync(FULLMASK, headacc, o);
    if (lane == 0) wsum[wib] = (double)headacc;
    __syncthreads();
    if (threadIdx.x == 0) {
        double s = 0.0;
        #pragma unroll
        for (int t = 0; t < 8; t++) s += wsum[t];
        g_part[blockIdx.x] = s;
    }
}

// final reduce over block partials
__global__ void k_final(const float* __restrict__ bl, float* __restrict__ out, int N) {
    __shared__ double sh[256];
    double s = 0.0;
    for (int i = threadIdx.x; i < PB_BLOCKS; i += 256) s += g_part[i];
    sh[threadIdx.x] = s;
    __syncthreads();
    for (int off = 128; off > 0; off >>= 1) {
        if (threadIdx.x < off) sh[threadIdx.x] += sh[threadIdx.x + off];
        __syncthreads();
    }
    if (threadIdx.x == 0) out[0] = (float)(sh[0] / (double)N) + bl[0];
}

// ---------------- launcher ----------------
// inputs: 0:x[N,2] f32  1:edge_index[2,E] int32/int64  2:W1[2,64]  3:b1[64]
//         4:W2[64,64]   5:b2[64]   6:Wl[64,1]  7:bl[1]
extern "C" void kernel_launch(void* const* d_in, const int* in_sizes, int n_in,
                              void* d_out, int out_size) {
    const float* x  = (const float*)d_in[0];
    const void*  ei = d_in[1];
    const float* W1 = (const float*)d_in[2];
    const float* b1 = (const float*)d_in[3];
    const float* W2 = (const float*)d_in[4];
    const float* b2 = (const float*)d_in[5];
    const float* Wl = (const float*)d_in[6];
    const float* bl = (const float*)d_in[7];
    float* out = (float*)d_out;

    int N = in_sizes[0] / 2;
    if (N > NMAX) N = NMAX;
    int E = in_sizes[1] / 2;
    if (E > EMAX) E = EMAX;
    int Equarter = (E + 3) / 4;
    int nodes_per_blk = 32;   // 8 warps * 4 nodes

    k_init <<<(N + 255) / 256, 256>>>(ei, E, (long long)N, N);
    k_build<<<(Equarter + 255) / 256, 256>>>(ei, E, N);
    k_dis  <<<(N + 255) / 256, 256>>>(x, N);
    k_passA<<<(N + nodes_per_blk - 1) / nodes_per_blk, 256>>>(N);
    k_passB<<<PB_BLOCKS, 256>>>(W1, b1, W2, b2, Wl, N);
    k_final<<<1, 256>>>(bl, out, N);
}